// round 7
// baseline (speedup 1.0000x reference)
#include <cuda_runtime.h>

typedef unsigned long long u64;
typedef unsigned int u32;

#define NB        8
#define NCLS      80
#define NCLASSES  (NB * NCLS)      // 640
#define KCAND     256
#define MAXPC     8
#define CAPS      640              // stored candidates per class
#define KR        20               // keys per lane
#define LOCCAP    24
#define CHUNK     256
#define THR       0.98f
#define WPB       4                // warps per NMS CTA
#define NBUCKETS  1024
#define BATCH     16               // pops per key/box/nms phase group
#define FULLM     0xFFFFFFFFu

static __device__ u64    g_cand[NCLASSES * CAPS];   // 3.3 MB scratch
static __device__ int    g_cnt[NCLASSES];           // reset by finisher each launch
static __device__ u64    g_keys[NCLASSES * MAXPC];  // (score<<32)|((0x7FFF-flat)<<16)|pos
static __device__ float4 g_boxes[NCLASSES * MAXPC];
static __device__ u32    g_done;

__device__ __forceinline__ float clamp01(float x) { return fminf(fmaxf(x, 0.0f), 1.0f); }
__device__ __forceinline__ u64 umax64(u64 a, u64 b) { return a > b ? a : b; }

// pairwise tree max over 20 registers
__device__ __forceinline__ u64 tmax20(const u64* k)
{
    u64 m0 = umax64(k[0], k[1]),   m1 = umax64(k[2], k[3]);
    u64 m2 = umax64(k[4], k[5]),   m3 = umax64(k[6], k[7]);
    u64 m4 = umax64(k[8], k[9]),   m5 = umax64(k[10], k[11]);
    u64 m6 = umax64(k[12], k[13]), m7 = umax64(k[14], k[15]);
    u64 m8 = umax64(k[16], k[17]), m9 = umax64(k[18], k[19]);
    u64 n0 = umax64(m0, m1), n1 = umax64(m2, m3);
    u64 n2 = umax64(m4, m5), n3 = umax64(m6, m7), n4 = umax64(m8, m9);
    return umax64(umax64(umax64(n0, n1), umax64(n2, n3)), n4);
}

// exact warp-wide u64 max via two REDUX.MAX.U32 phases (all lanes participate)
__device__ __forceinline__ u64 warpmax64(u64 v)
{
    u32 hi = (u32)(v >> 32);
    u32 hmax = __reduce_max_sync(FULLM, hi);
    u32 lo = (hi == hmax) ? (u32)v : 0u;
    u32 lmax = __reduce_max_sync(FULLM, lo);
    return ((u64)hmax << 32) | lmax;
}

// ---------------------------------------------------------------------------
// Kernel A: coalesced scan; capture s >= THR into compacted per-class lists.
// ---------------------------------------------------------------------------
__global__ __launch_bounds__(256) void scan_kernel(
    const float* __restrict__ scores, int nbox, int nchunks)
{
    const int tid  = threadIdx.x;
    const int b    = blockIdx.x / nchunks;
    const int ch   = blockIdx.x % nchunks;
    const int box0 = ch * CHUNK;
    const int boxN = min(CHUNK, nbox - box0);

    __shared__ u64 loc[NCLS * LOCCAP];   // 15 KB
    __shared__ int lcnt[NCLS];

    for (int i = tid; i < NCLS; i += 256) lcnt[i] = 0;
    __syncthreads();

    if (boxN > 0) {
        const float4* sp = reinterpret_cast<const float4*>(scores) +
                           (size_t)(b * nbox + box0) * (NCLS / 4);
        const int nf4 = boxN * (NCLS / 4);
        for (int t = tid; t < nf4; t += 256) {
            float4 v = sp[t];
            int box = box0 + t / (NCLS / 4);
            int g   = t % (NCLS / 4);
            float sv[4] = {v.x, v.y, v.z, v.w};
            #pragma unroll
            for (int k = 0; k < 4; ++k) {
                if (sv[k] >= THR) {
                    int c = g * 4 + k;
                    u64 key = ((u64)__float_as_uint(sv[k]) << 32) |
                              (u32)(0xFFFFFFFFu - (u32)box);
                    int p = atomicAdd(&lcnt[c], 1);
                    if (p < LOCCAP) {
                        loc[c * LOCCAP + p] = key;
                    } else {  // rare spill straight to global (set stays complete)
                        int q = atomicAdd(&g_cnt[b * NCLS + c], 1);
                        if (q < CAPS) g_cand[(size_t)(b * NCLS + c) * CAPS + q] = key;
                    }
                }
            }
        }
    }
    __syncthreads();

    for (int c = tid; c < NCLS; c += 256) {
        int n = min(lcnt[c], LOCCAP);
        if (n > 0) {
            int base = atomicAdd(&g_cnt[b * NCLS + c], n);
            for (int j = 0; j < n; ++j) {
                int q = base + j;
                if (q < CAPS) g_cand[(size_t)(b * NCLS + c) * CAPS + q] = loc[c * LOCCAP + j];
            }
        }
    }
}

// ---------------------------------------------------------------------------
// Kernel B: one warp per (batch,class); batched key-pop / box-gather / NMS.
// All warp collectives execute under uniform control flow.
// ---------------------------------------------------------------------------
__global__ __launch_bounds__(32 * WPB) void nms_kernel(
    const float4* __restrict__ boxes4,
    const float*  __restrict__ scores,
    float* __restrict__ out,
    int nbox)
{
    const int tid  = threadIdx.x;
    const int lane = tid & 31;
    const int wid  = tid >> 5;
    const int cls  = blockIdx.x * WPB + wid;
    const int b    = cls / NCLS;
    const int c    = cls % NCLS;

    __shared__ u32 sh_hist[WPB][NBUCKETS];   // fallback only, 16 KB
    __shared__ int sh_fc[WPB];
    __shared__ int sh_last;

    int cnt = g_cnt[cls];

    if (!(cnt >= KCAND && cnt <= CAPS)) {
        // ---- exact warp-level fallback: recompute candidates into g_cand ----
        u32* hist = sh_hist[wid];
        for (int i = lane; i < NBUCKETS; i += 32) hist[i] = 0;
        __syncwarp();
        for (int i = lane; i < nbox; i += 32) {
            float s = scores[((size_t)b * nbox + i) * NCLS + c];
            atomicAdd(&hist[min((int)(s * (float)NBUCKETS), NBUCKETS - 1)], 1u);
        }
        __syncwarp();
        const int base = lane * 32;
        u32 part = 0;
        #pragma unroll
        for (int j = 0; j < 32; ++j) part += hist[base + j];
        u32 suf = part;
        #pragma unroll
        for (int off = 16; off; off >>= 1) {
            u32 v = __shfl_down_sync(FULLM, suf, off);
            if (lane + off < 32) suf += v;
        }
        u32 above = __shfl_down_sync(FULLM, suf, 1);
        if (lane == 31) above = 0;
        int T = -1;
        u32 prev = above;
        for (int bkt = base + 31; bkt >= base; --bkt) {
            u32 cur = prev + hist[bkt];
            if (cur >= KCAND && prev < KCAND) T = bkt;
            prev = cur;
        }
        #pragma unroll
        for (int off = 16; off; off >>= 1)
            T = max(T, __shfl_xor_sync(FULLM, T, off));
        T = max(T, 0);
        if (lane == 0) sh_fc[wid] = 0;
        __syncwarp();
        for (int i = lane; i < nbox; i += 32) {
            float s = scores[((size_t)b * nbox + i) * NCLS + c];
            int bk = min((int)(s * (float)NBUCKETS), NBUCKETS - 1);
            if (bk >= T) {
                int q = atomicAdd(&sh_fc[wid], 1);
                if (q < CAPS)
                    g_cand[(size_t)cls * CAPS + q] =
                        ((u64)__float_as_uint(s) << 32) |
                        (u32)(0xFFFFFFFFu - (u32)i);
            }
        }
        __threadfence();
        __syncwarp();
        cnt = min(sh_fc[wid], CAPS);
    }

    // ---- load keys into registers ----
    u64 kr[KR];
    #pragma unroll
    for (int r = 0; r < KR; ++r) {
        int slot = r * 32 + lane;
        kr[r] = (slot < cnt) ? g_cand[(size_t)cls * CAPS + slot] : 0ull;
    }
    u64 mymax = tmax20(kr);

    float4 mykept = make_float4(0.f, 0.f, 0.f, 0.f);
    float  myka   = 0.f;
    int kc = 0, totpops = 0;
    bool more = true;

    while (more && kc < MAXPC && totpops < KCAND) {
        // ---- phase 1: pop up to BATCH keys, no memory on critical path ----
        const int lim = min(BATCH, KCAND - totpops);
        u64 okey = 0ull;
        int n = 0;
        for (int r = 0; r < lim; ++r) {
            u64 best = warpmax64(mymax);                  // uniform result
            if ((u32)(best >> 32) <= 0x3F000000u) break;  // uniform break
            if (lane == r) okey = best;
            if (mymax == best) {   // unique owner refills its lane max
                #pragma unroll
                for (int q = 0; q < KR; ++q)
                    if (kr[q] == best) kr[q] = 0ull;
                mymax = tmax20(kr);
            }
            ++n;
        }
        more = (n == lim) && (lim == BATCH);

        // ---- phase 2: one parallel box gather (MLP = n) ----
        float4 obox = make_float4(0.f, 0.f, 0.f, 0.f);
        if (lane < n) {
            u32 bi = 0xFFFFFFFFu - (u32)okey;
            obox = boxes4[(size_t)b * nbox + bi];
        }

        // ---- phase 3: shuffle-resident greedy NMS over ordered batch ----
        for (int r = 0; r < n; ++r) {
            // all collectives below execute unconditionally by the full warp
            float4 bx;
            bx.x = __shfl_sync(FULLM, obox.x, r);
            bx.y = __shfl_sync(FULLM, obox.y, r);
            bx.z = __shfl_sync(FULLM, obox.z, r);
            bx.w = __shfl_sync(FULLM, obox.w, r);
            u64 key = __shfl_sync(FULLM, okey, r);        // hoisted (was the R6 hang)
            float area = fmaxf(bx.z - bx.x, 0.f) * fmaxf(bx.w - bx.y, 0.f);

            bool supme = false;
            if (lane < kc) {
                float iy1 = fmaxf(bx.x, mykept.x), ix1 = fmaxf(bx.y, mykept.y);
                float iy2 = fminf(bx.z, mykept.z), ix2 = fminf(bx.w, mykept.w);
                float inter = fmaxf(iy2 - iy1, 0.f) * fmaxf(ix2 - ix1, 0.f);
                float uni = area + myka - inter;
                float iou = (uni > 0.f) ? inter / uni : 0.f;
                supme = iou > 0.5f;
            }
            bool keep = (__ballot_sync(FULLM, supme) == 0u);   // uniform

            if (keep) {
                if (lane == kc) {
                    mykept = bx;
                    myka = area;
                    int flat = c * KCAND + totpops + r;
                    int pos  = c * MAXPC + kc;
                    g_keys[b * NCLS * MAXPC + pos] =
                        ((u64)(u32)(key >> 32) << 32) |
                        ((u64)(u32)(0x7FFF - flat) << 16) | (u32)pos;
                    g_boxes[b * NCLS * MAXPC + pos] = bx;
                }
                ++kc;
                if (kc >= MAXPC) { totpops += r + 1; goto nms_done; }  // uniform
            }
        }
        totpops += n;
    }
nms_done:
    if (lane >= kc && lane < MAXPC)
        g_keys[(size_t)cls * MAXPC + lane] = 0ull;

    // ---- fused finisher: last CTA does per-batch top-8 + counter reset ----
    __syncthreads();
    if (tid == 0) {
        __threadfence();
        sh_last = (atomicAdd(&g_done, 1u) == (u32)(gridDim.x - 1));
    }
    __syncthreads();
    if (!sh_last) return;
    if (tid == 0) g_done = 0u;
    for (int i = tid; i < NCLASSES; i += 32 * WPB) g_cnt[i] = 0;
    __threadfence();

    for (int bb = wid; bb < NB; bb += WPB) {
        // per-lane insertion top-8 over its 20 keys, then 8 redux merges
        u64 t[8] = {0, 0, 0, 0, 0, 0, 0, 0};
        #pragma unroll
        for (int j = 0; j < 20; ++j) {
            u64 k = g_keys[(size_t)bb * (NCLS * MAXPC) + j * 32 + lane];
            #pragma unroll
            for (int p = 0; p < 8; ++p)
                if (k > t[p]) { u64 tmp = t[p]; t[p] = k; k = tmp; }
        }

        u64 mykey = 0ull;
        #pragma unroll
        for (int r = 0; r < 8; ++r) {
            u64 best = warpmax64(t[0]);
            if (lane == r) mykey = best;
            if (t[0] == best) {
                #pragma unroll
                for (int p = 0; p < 7; ++p) t[p] = t[p + 1];
                t[7] = 0ull;
            }
        }

        float s = __uint_as_float((u32)(mykey >> 32));
        bool mask = s > 0.0f;
        if (lane < 8) {
            float4 bx = make_float4(0.f, 0.f, 0.f, 0.f);
            float fcls = 0.f;
            if (mask) {
                int pos  = (int)(mykey & 0xFFFFu);
                int flat = 0x7FFF - (int)((mykey >> 16) & 0x7FFFu);
                fcls = (float)(flat / KCAND);
                float4 gb = g_boxes[(size_t)bb * (NCLS * MAXPC) + pos];
                bx.x = clamp01(gb.x); bx.y = clamp01(gb.y);
                bx.z = clamp01(gb.z); bx.w = clamp01(gb.w);
            }
            int ob = (bb * 8 + lane) * 4;
            out[ob + 0] = bx.x; out[ob + 1] = bx.y;
            out[ob + 2] = bx.z; out[ob + 3] = bx.w;
            out[NB * 8 * 4 + bb * 8 + lane]          = mask ? s : 0.f;    // scores  @256
            out[NB * 8 * 4 + NB * 8 + bb * 8 + lane] = mask ? fcls : 0.f; // classes @320
        }
        u32 vb = __ballot_sync(FULLM, (lane < 8) && mask);
        if (lane == 0)
            out[NB * 8 * 4 + 2 * NB * 8 + bb] = (float)__popc(vb);        // valid @384
    }
}

// ---------------------------------------------------------------------------
extern "C" void kernel_launch(void* const* d_in, const int* in_sizes, int n_in,
                              void* d_out, int out_size)
{
    const float* boxes  = (const float*)d_in[0];
    const float* scores = (const float*)d_in[1];
    int nbox = in_sizes[0] / (NB * 4);
    int nchunks = (nbox + CHUNK - 1) / CHUNK;

    scan_kernel<<<NB * nchunks, 256>>>(scores, nbox, nchunks);
    nms_kernel<<<NCLASSES / WPB, 32 * WPB>>>((const float4*)boxes, scores,
                                             (float*)d_out, nbox);
}

// round 8
// speedup vs baseline: 1.3389x; 1.3389x over previous
#include <cuda_runtime.h>

typedef unsigned long long u64;
typedef unsigned int u32;

#define NB        8
#define NCLS      80
#define NCLASSES  (NB * NCLS)      // 640
#define KCAND     256
#define MAXPC     8
#define CSTRIDE   640              // per-class slot stride in g_cand (fallback capacity)
#define CAPSC     128              // trusted capture bound (E=64, sigma=8 -> 8 sigma)
#define KRC       4                // keys/lane, common path
#define KRF       20               // keys/lane, fallback path
#define LOCCAP    8
#define CHUNK     256
#define THR       0.9968f          // E[captures/class] = 64
#define WPB       4                // warps per NMS CTA
#define NBUCKETS  1024
#define BATCH     16
#define FULLM     0xFFFFFFFFu

static __device__ u64    g_cand[NCLASSES * CSTRIDE];  // 3.3 MB scratch
static __device__ int    g_cnt[NCLASSES];             // reset by finisher each launch
static __device__ u64    g_keys[NCLASSES * MAXPC];    // (score<<32)|((0x7FFF-flat)<<16)|pos
static __device__ float4 g_boxes[NCLASSES * MAXPC];
static __device__ u32    g_done;

__device__ __forceinline__ float clamp01(float x) { return fminf(fmaxf(x, 0.0f), 1.0f); }
__device__ __forceinline__ u64 umax64(u64 a, u64 b) { return a > b ? a : b; }

// exact warp-wide u64 max via two REDUX.MAX.U32 phases (all lanes participate)
__device__ __forceinline__ u64 warpmax64(u64 v)
{
    u32 hi = (u32)(v >> 32);
    u32 hmax = __reduce_max_sync(FULLM, hi);
    u32 lo = (hi == hmax) ? (u32)v : 0u;
    u32 lmax = __reduce_max_sync(FULLM, lo);
    return ((u64)hmax << 32) | lmax;
}

// ---------------------------------------------------------------------------
// Warp-synchronous greedy NMS over a candidate list (exact rank order).
// Returns kept count; *ranout set if list exhausted before 8 keeps / 256 pops.
// ---------------------------------------------------------------------------
template<int KRN>
__device__ int run_nms(const float4* __restrict__ boxes4, int nbox, int b, int c,
                       const u64* __restrict__ cand, int cnt, bool* ranout)
{
    const int lane = threadIdx.x & 31;

    u64 kr[KRN];
    #pragma unroll
    for (int r = 0; r < KRN; ++r) {
        int slot = r * 32 + lane;
        kr[r] = (slot < cnt) ? cand[slot] : 0ull;
    }
    u64 mymax = kr[0];
    #pragma unroll
    for (int r = 1; r < KRN; ++r) mymax = umax64(mymax, kr[r]);

    float4 mykept = make_float4(0.f, 0.f, 0.f, 0.f);
    float  myka   = 0.f;
    int kc = 0, totpops = 0;
    bool more = true, exhausted = false;

    while (more && kc < MAXPC && totpops < KCAND) {
        // ---- phase 1: pop up to BATCH keys (no memory on critical path) ----
        const int lim = min(BATCH, KCAND - totpops);
        u64 okey = 0ull;
        int n = 0;
        for (int r = 0; r < lim; ++r) {
            u64 best = warpmax64(mymax);                  // uniform
            if ((u32)(best >> 32) <= 0x3F000000u) { exhausted = true; break; }
            if (lane == r) okey = best;
            if (mymax == best) {   // unique owner refills its lane max
                mymax = 0ull;
                #pragma unroll
                for (int q = 0; q < KRN; ++q) {
                    if (kr[q] == best) kr[q] = 0ull;
                    mymax = umax64(mymax, kr[q]);
                }
            }
            ++n;
        }
        more = (n == lim) && (lim == BATCH);

        // ---- phase 2: one parallel box gather (MLP = n) ----
        float4 obox = make_float4(0.f, 0.f, 0.f, 0.f);
        if (lane < n) {
            u32 bi = 0xFFFFFFFFu - (u32)okey;
            obox = boxes4[(size_t)b * nbox + bi];
        }

        // ---- phase 3: shuffle-resident greedy NMS over ordered batch ----
        for (int r = 0; r < n; ++r) {
            float4 bx;
            bx.x = __shfl_sync(FULLM, obox.x, r);
            bx.y = __shfl_sync(FULLM, obox.y, r);
            bx.z = __shfl_sync(FULLM, obox.z, r);
            bx.w = __shfl_sync(FULLM, obox.w, r);
            u64 key = __shfl_sync(FULLM, okey, r);
            float area = fmaxf(bx.z - bx.x, 0.f) * fmaxf(bx.w - bx.y, 0.f);

            bool supme = false;
            if (lane < kc) {
                float iy1 = fmaxf(bx.x, mykept.x), ix1 = fmaxf(bx.y, mykept.y);
                float iy2 = fminf(bx.z, mykept.z), ix2 = fminf(bx.w, mykept.w);
                float inter = fmaxf(iy2 - iy1, 0.f) * fmaxf(ix2 - ix1, 0.f);
                float uni = area + myka - inter;
                float iou = (uni > 0.f) ? inter / uni : 0.f;
                supme = iou > 0.5f;
            }
            bool keep = (__ballot_sync(FULLM, supme) == 0u);   // uniform

            if (keep) {
                if (lane == kc) {
                    mykept = bx;
                    myka = area;
                    int flat = c * KCAND + totpops + r;
                    int pos  = c * MAXPC + kc;
                    g_keys[b * NCLS * MAXPC + pos] =
                        ((u64)(u32)(key >> 32) << 32) |
                        ((u64)(u32)(0x7FFF - flat) << 16) | (u32)pos;
                    g_boxes[b * NCLS * MAXPC + pos] = bx;
                }
                ++kc;
                if (kc >= MAXPC) return kc;    // uniform exit, no ranout
            }
        }
        totpops += n;
        if (exhausted) break;
    }
    *ranout = exhausted && (kc < MAXPC) && (totpops < KCAND);
    return kc;
}

// ---------------------------------------------------------------------------
// Kernel A: coalesced MLP-4 scan; capture s >= THR into per-class lists.
// ---------------------------------------------------------------------------
__global__ __launch_bounds__(256) void scan_kernel(
    const float* __restrict__ scores, int nbox, int nchunks)
{
    const int tid  = threadIdx.x;
    const int b    = blockIdx.x / nchunks;
    const int ch   = blockIdx.x % nchunks;
    const int box0 = ch * CHUNK;
    const int boxN = min(CHUNK, nbox - box0);

    __shared__ u64 loc[NCLS * LOCCAP];   // 5 KB
    __shared__ int lcnt[NCLS];

    for (int i = tid; i < NCLS; i += 256) lcnt[i] = 0;
    __syncthreads();

    if (boxN > 0) {
        const float4* sp = reinterpret_cast<const float4*>(scores) +
                           (size_t)(b * nbox + box0) * (NCLS / 4);
        const int nf4 = boxN * (NCLS / 4);
        for (int t0 = tid; t0 < nf4; t0 += 1024) {
            // 4 independent loads in flight (MLP=4)
            float4 v[4];
            #pragma unroll
            for (int u = 0; u < 4; ++u) {
                int t = t0 + u * 256;
                v[u] = (t < nf4) ? sp[t]
                                 : make_float4(0.f, 0.f, 0.f, 0.f);
            }
            #pragma unroll
            for (int u = 0; u < 4; ++u) {
                int t = t0 + u * 256;
                if (t >= nf4) break;
                int box = box0 + t / (NCLS / 4);
                int g   = t % (NCLS / 4);
                float sv[4] = {v[u].x, v[u].y, v[u].z, v[u].w};
                #pragma unroll
                for (int k = 0; k < 4; ++k) {
                    if (sv[k] >= THR) {
                        int c = g * 4 + k;
                        u64 key = ((u64)__float_as_uint(sv[k]) << 32) |
                                  (u32)(0xFFFFFFFFu - (u32)box);
                        int p = atomicAdd(&lcnt[c], 1);
                        if (p < LOCCAP) {
                            loc[c * LOCCAP + p] = key;
                        } else {  // rare spill to global (set stays complete)
                            int q = atomicAdd(&g_cnt[b * NCLS + c], 1);
                            if (q < CSTRIDE)
                                g_cand[(size_t)(b * NCLS + c) * CSTRIDE + q] = key;
                        }
                    }
                }
            }
        }
    }
    __syncthreads();

    for (int c = tid; c < NCLS; c += 256) {
        int n = min(lcnt[c], LOCCAP);
        if (n > 0) {
            int base = atomicAdd(&g_cnt[b * NCLS + c], n);
            for (int j = 0; j < n; ++j) {
                int q = base + j;
                if (q < CSTRIDE)
                    g_cand[(size_t)(b * NCLS + c) * CSTRIDE + q] = loc[c * LOCCAP + j];
            }
        }
    }
}

// ---------------------------------------------------------------------------
// Kernel B: one warp per (batch,class); small-window NMS + fused finisher.
// ---------------------------------------------------------------------------
__global__ __launch_bounds__(32 * WPB) void nms_kernel(
    const float4* __restrict__ boxes4,
    const float*  __restrict__ scores,
    float* __restrict__ out,
    int nbox)
{
    const int tid  = threadIdx.x;
    const int lane = tid & 31;
    const int wid  = tid >> 5;
    const int cls  = blockIdx.x * WPB + wid;
    const int b    = cls / NCLS;
    const int c    = cls % NCLS;

    __shared__ u32 sh_hist[WPB][NBUCKETS];   // fallback only, 16 KB
    __shared__ int sh_fc[WPB];
    __shared__ int sh_last;

    const u64* cand = g_cand + (size_t)cls * CSTRIDE;
    int cnt = g_cnt[cls];
    int kc = 0;
    bool needfb = (cnt > CAPSC) || (cnt <= 0);

    if (!needfb) {
        bool ranout = false;
        kc = run_nms<KRC>(boxes4, nbox, b, c, cand, cnt, &ranout);
        needfb = ranout;   // exhausted small window before 8 keeps / 256 pops
    }

    if (needfb) {
        // ---- exact fallback: histogram top-256 window rescan (never expected) ----
        u32* hist = sh_hist[wid];
        for (int i = lane; i < NBUCKETS; i += 32) hist[i] = 0;
        __syncwarp();
        for (int i = lane; i < nbox; i += 32) {
            float s = scores[((size_t)b * nbox + i) * NCLS + c];
            atomicAdd(&hist[min((int)(s * (float)NBUCKETS), NBUCKETS - 1)], 1u);
        }
        __syncwarp();
        const int base = lane * 32;
        u32 part = 0;
        #pragma unroll
        for (int j = 0; j < 32; ++j) part += hist[base + j];
        u32 suf = part;
        #pragma unroll
        for (int off = 16; off; off >>= 1) {
            u32 v = __shfl_down_sync(FULLM, suf, off);
            if (lane + off < 32) suf += v;
        }
        u32 above = __shfl_down_sync(FULLM, suf, 1);
        if (lane == 31) above = 0;
        int T = -1;
        u32 prev = above;
        for (int bkt = base + 31; bkt >= base; --bkt) {
            u32 cur = prev + hist[bkt];
            if (cur >= KCAND && prev < KCAND) T = bkt;
            prev = cur;
        }
        #pragma unroll
        for (int off = 16; off; off >>= 1)
            T = max(T, __shfl_xor_sync(FULLM, T, off));
        T = max(T, 0);
        if (lane == 0) sh_fc[wid] = 0;
        __syncwarp();
        for (int i = lane; i < nbox; i += 32) {
            float s = scores[((size_t)b * nbox + i) * NCLS + c];
            int bk = min((int)(s * (float)NBUCKETS), NBUCKETS - 1);
            if (bk >= T) {
                int q = atomicAdd(&sh_fc[wid], 1);
                if (q < CSTRIDE)
                    g_cand[(size_t)cls * CSTRIDE + q] =
                        ((u64)__float_as_uint(s) << 32) |
                        (u32)(0xFFFFFFFFu - (u32)i);
            }
        }
        __threadfence();
        __syncwarp();
        int fcnt = min(sh_fc[wid], CSTRIDE);
        bool dummy = false;
        kc = run_nms<KRF>(boxes4, nbox, b, c, cand, fcnt, &dummy);
    }

    if (lane >= kc && lane < MAXPC)
        g_keys[(size_t)cls * MAXPC + lane] = 0ull;

    // ---- fused finisher: last CTA does per-batch top-8 + counter reset ----
    __syncthreads();
    if (tid == 0) {
        __threadfence();
        sh_last = (atomicAdd(&g_done, 1u) == (u32)(gridDim.x - 1));
    }
    __syncthreads();
    if (!sh_last) return;
    if (tid == 0) g_done = 0u;
    for (int i = tid; i < NCLASSES; i += 32 * WPB) g_cnt[i] = 0;
    __threadfence();

    for (int bb = wid; bb < NB; bb += WPB) {
        // per-lane insertion top-8 over its 20 keys, then 8 redux merges
        u64 t[8] = {0, 0, 0, 0, 0, 0, 0, 0};
        #pragma unroll
        for (int j = 0; j < 20; ++j) {
            u64 k = g_keys[(size_t)bb * (NCLS * MAXPC) + j * 32 + lane];
            #pragma unroll
            for (int p = 0; p < 8; ++p)
                if (k > t[p]) { u64 tmp = t[p]; t[p] = k; k = tmp; }
        }

        u64 mykey = 0ull;
        #pragma unroll
        for (int r = 0; r < 8; ++r) {
            u64 best = warpmax64(t[0]);
            if (lane == r) mykey = best;
            if (t[0] == best) {
                #pragma unroll
                for (int p = 0; p < 7; ++p) t[p] = t[p + 1];
                t[7] = 0ull;
            }
        }

        float s = __uint_as_float((u32)(mykey >> 32));
        bool mask = s > 0.0f;
        if (lane < 8) {
            float4 bx = make_float4(0.f, 0.f, 0.f, 0.f);
            float fcls = 0.f;
            if (mask) {
                int pos  = (int)(mykey & 0xFFFFu);
                int flat = 0x7FFF - (int)((mykey >> 16) & 0x7FFFu);
                fcls = (float)(flat / KCAND);
                float4 gb = g_boxes[(size_t)bb * (NCLS * MAXPC) + pos];
                bx.x = clamp01(gb.x); bx.y = clamp01(gb.y);
                bx.z = clamp01(gb.z); bx.w = clamp01(gb.w);
            }
            int ob = (bb * 8 + lane) * 4;
            out[ob + 0] = bx.x; out[ob + 1] = bx.y;
            out[ob + 2] = bx.z; out[ob + 3] = bx.w;
            out[NB * 8 * 4 + bb * 8 + lane]          = mask ? s : 0.f;    // scores  @256
            out[NB * 8 * 4 + NB * 8 + bb * 8 + lane] = mask ? fcls : 0.f; // classes @320
        }
        u32 vb = __ballot_sync(FULLM, (lane < 8) && mask);
        if (lane == 0)
            out[NB * 8 * 4 + 2 * NB * 8 + bb] = (float)__popc(vb);        // valid @384
    }
}

// ---------------------------------------------------------------------------
extern "C" void kernel_launch(void* const* d_in, const int* in_sizes, int n_in,
                              void* d_out, int out_size)
{
    const float* boxes  = (const float*)d_in[0];
    const float* scores = (const float*)d_in[1];
    int nbox = in_sizes[0] / (NB * 4);
    int nchunks = (nbox + CHUNK - 1) / CHUNK;

    scan_kernel<<<NB * nchunks, 256>>>(scores, nbox, nchunks);
    nms_kernel<<<NCLASSES / WPB, 32 * WPB>>>((const float4*)boxes, scores,
                                             (float*)d_out, nbox);
}